// round 16
// baseline (speedup 1.0000x reference)
#include <cuda_runtime.h>
#include <cuda_fp16.h>
#include <cstdint>

#define N_BATCH 1024
#define T_STEPS 64
#define D_IN    512
#define H_DIM   1024
#define G4      4096
#define K2      2048

__device__ __half g_XW [(size_t)N_BATCH * T_STEPS * G4];
__device__ __half g_x  [(size_t)N_BATCH * T_STEPS * D_IN];
__device__ __half g_Wxp[(size_t)G4 * D_IN];
__device__ __half g_Wcp[(size_t)G4 * K2];
__device__ __half g_A2 [(size_t)N_BATCH * K2];
__device__ __half g_Af16[(size_t)N_BATCH * H_DIM * 16];
__device__ float  g_c  [(size_t)N_BATCH * H_DIM];
__device__ __half g_hw [(size_t)N_BATCH * G4];
__device__ unsigned int g_cntA[8];   // hw-ready per bm block
__device__ unsigned int g_cntB[8];   // A2-ready per bm block

// ---- helpers ----
__device__ __forceinline__ uint32_t s2u(const void* p) {
    uint32_t a;
    asm("{.reg .u64 t; cvta.to.shared.u64 t, %1; cvt.u32.u64 %0, t;}" : "=r"(a) : "l"(p));
    return a;
}
#define SW128(o) ((o) ^ (((o) >> 3) & 0x70))
__device__ __forceinline__ void cpa(uint32_t s, const void* g) {
    asm volatile("cp.async.cg.shared.global [%0], [%1], 16;" :: "r"(s), "l"(g));
}
#define CP_COMMIT() asm volatile("cp.async.commit_group;" ::: "memory")
#define CP_WAIT1()  asm volatile("cp.async.wait_group 1;" ::: "memory")

__device__ __forceinline__ void mma16816(float* c, const uint32_t* a, const uint32_t* b) {
    asm volatile("mma.sync.aligned.m16n8k16.row.col.f32.f16.f16.f32 "
        "{%0,%1,%2,%3}, {%4,%5,%6,%7}, {%8,%9}, {%0,%1,%2,%3};"
        : "+f"(c[0]), "+f"(c[1]), "+f"(c[2]), "+f"(c[3])
        : "r"(a[0]), "r"(a[1]), "r"(a[2]), "r"(a[3]), "r"(b[0]), "r"(b[1]));
}
__device__ __forceinline__ void ldsm4(uint32_t* r, uint32_t a) {
    asm volatile("ldmatrix.sync.aligned.m8n8.x4.shared.b16 {%0,%1,%2,%3}, [%4];"
        : "=r"(r[0]), "=r"(r[1]), "=r"(r[2]), "=r"(r[3]) : "r"(a));
}
__device__ __forceinline__ void ldsm2(uint32_t* r, uint32_t a) {
    asm volatile("ldmatrix.sync.aligned.m8n8.x2.shared.b16 {%0,%1}, [%2];"
        : "=r"(r[0]), "=r"(r[1]) : "r"(a));
}
__device__ __forceinline__ float sigf(float x) { return 1.f / (1.f + __expf(-x)); }

__device__ __forceinline__ void spin_ge(const unsigned int* p, unsigned target) {
    unsigned v;
    do {
        asm volatile("ld.acquire.gpu.u32 %0, [%1];" : "=r"(v) : "l"(p) : "memory");
        if (v < target) __nanosleep(64);
    } while (v < target);
}

// ===== XW GEMM: 128x128, BK=64, 3-stage, 1 MMA, fp16 output =================
#define GSMEM (3 * 32768)
__global__ void __launch_bounds__(256, 1)
gemm_xw_kernel(const __half* __restrict__ A, int lda,
               const __half* __restrict__ B, int ldb,
               const float* __restrict__ bias, __half* __restrict__ C, int K, int Nc) {
    extern __shared__ char smx[];
    const uint32_t sb = s2u(smx);
    const int tid = threadIdx.x, wid = tid >> 5, lane = tid & 31;
    const int bm = blockIdx.y * 128, bn = blockIdx.x * 128;
    const int wm = (wid >> 2) * 64, wn = (wid & 3) * 32;

    uint32_t so[4];
#pragma unroll
    for (int i = 0; i < 4; i++)
        so[i] = SW128((uint32_t)(((tid >> 3) + i * 32) * 128 + (tid & 7) * 16));

    const int KT = K / 64;
    float acc[4][4][4];
#pragma unroll
    for (int mt = 0; mt < 4; mt++)
#pragma unroll
        for (int nt = 0; nt < 4; nt++)
#pragma unroll
            for (int v = 0; v < 4; v++) acc[mt][nt][v] = 0.f;

    auto load_stage = [&](int kt, int st) {
        if (kt < KT) {
            uint32_t s0 = sb + st * 32768;
#pragma unroll
            for (int i = 0; i < 4; i++) {
                int r = (tid >> 3) + i * 32;
                size_t ga = (size_t)(bm + r) * lda + kt * 64 + (tid & 7) * 8;
                size_t gb = (size_t)(bn + r) * ldb + kt * 64 + (tid & 7) * 8;
                cpa(s0 + so[i],         A + ga);
                cpa(s0 + 16384 + so[i], B + gb);
            }
        }
        CP_COMMIT();
    };

    load_stage(0, 0);
    load_stage(1, 1);

    const int arow  = wm + (lane & 7) + ((lane >> 3) & 1) * 8;
    const int acolb = ((lane >> 4) & 1) * 16;
    const int brow  = wn + (lane & 7);
    const int bcolb = ((lane >> 3) & 1) * 16;

    for (int kt = 0; kt < KT; kt++) {
        CP_WAIT1();
        __syncthreads();
        load_stage(kt + 2, (kt + 2) % 3);

        uint32_t s0 = sb + (kt % 3) * 32768;
#pragma unroll
        for (int ks = 0; ks < 4; ks++) {
            uint32_t ah[4][4], bh[4][2];
#pragma unroll
            for (int mt = 0; mt < 4; mt++) {
                uint32_t off = SW128((uint32_t)((arow + mt * 16) * 128 + ks * 32 + acolb));
                ldsm4(ah[mt], s0 + off);
            }
#pragma unroll
            for (int nt = 0; nt < 4; nt++) {
                uint32_t off = SW128((uint32_t)((brow + nt * 8) * 128 + ks * 32 + bcolb));
                ldsm2(bh[nt], s0 + 16384 + off);
            }
#pragma unroll
            for (int mt = 0; mt < 4; mt++)
#pragma unroll
                for (int nt = 0; nt < 4; nt++)
                    mma16816(acc[mt][nt], ah[mt], bh[nt]);
        }
        __syncthreads();
    }

    const int q = lane >> 2, i2 = (lane & 3) * 2;
#pragma unroll
    for (int mt = 0; mt < 4; mt++) {
        int row0 = bm + wm + mt * 16 + q;
#pragma unroll
        for (int nt = 0; nt < 4; nt++) {
            int col = bn + wn + nt * 8 + i2;
            float2 bb = *(const float2*)(bias + col);
            *(__half2*)(C + (size_t)row0 * Nc + col) =
                __floats2half2_rn(acc[mt][nt][0] + bb.x, acc[mt][nt][1] + bb.y);
            *(__half2*)(C + (size_t)(row0 + 8) * Nc + col) =
                __floats2half2_rn(acc[mt][nt][2] + bb.x, acc[mt][nt][3] + bb.y);
        }
    }
}

// ===== PERSISTENT STEP LOOP: 128 CTAs, per-block producer/consumer counters ==
#define GSMEM2 (3 * 49152)
__global__ void __launch_bounds__(512, 1)
persist_kernel(__half* __restrict__ A2, const __half* __restrict__ B,
               __half* __restrict__ hw,
               const __half* __restrict__ XW,
               const __half* __restrict__ Af16,
               float* __restrict__ c,
               float* __restrict__ out) {
    extern __shared__ char smx[];
    const uint32_t sb = s2u(smx);
    const int tid = threadIdx.x, wid = tid >> 5, lane = tid & 31;
    const int bid = (int)blockIdx.x;
    const int bm = (bid & 7) * 128, bn = (bid >> 3) * 256;
    const int wm = (wid >> 3) * 64, wn = (wid & 7) * 32;
    const int KT = K2 / 64;
    const int n0 = bid * 8;                    // lstm rows n0..n0+7
    const int nb = bid >> 4;                   // bm-block containing those rows

    uint32_t soA[2], soB[4];
#pragma unroll
    for (int i = 0; i < 2; i++) {
        int u = tid + i * 512;
        soA[i] = SW128((uint32_t)((u >> 3) * 128 + (u & 7) * 16));
    }
#pragma unroll
    for (int i = 0; i < 4; i++) {
        int u = tid + i * 512;
        soB[i] = SW128((uint32_t)((u >> 3) * 128 + (u & 7) * 16));
    }

    const int arow  = wm + (lane & 7) + ((lane >> 3) & 1) * 8;
    const int acolb = ((lane >> 4) & 1) * 16;
    const int brow  = wn + (lane & 7);
    const int bcolb = ((lane >> 3) & 1) * 16;
    const int q = lane >> 2, i2 = (lane & 3) * 2;

    const int row = tid >> 6;                  // 0..7 (lstm row within block)
    const int l64 = tid & 63;
    const int n = n0 + row;
    const __half* hwr = hw + (size_t)n * G4;
    const __half* Afr = Af16 + (size_t)n * (H_DIM * 16);

    float* red = (float*)smx;                  // 8 x 16 floats
    float* wsh = red + 128;

    for (int t = 0; t < T_STEPS; t++) {
        // ---- wait: A2 rows for my bm block produced by step t-1 lstm --------
        if (t > 0) {
            if (tid == 0) spin_ge(g_cntB + (bid & 7), 16u * (unsigned)t);
            __syncthreads();
        }

        // ---------------- GEMM phase ----------------
        float acc[4][4][4];
#pragma unroll
        for (int mt = 0; mt < 4; mt++)
#pragma unroll
            for (int nt = 0; nt < 4; nt++)
#pragma unroll
                for (int v = 0; v < 4; v++) acc[mt][nt][v] = 0.f;

        auto load_stage = [&](int kt, int st) {
            if (kt < KT) {
                uint32_t s0 = sb + st * 49152;
#pragma unroll
                for (int i = 0; i < 2; i++) {
                    int u = tid + i * 512;
                    size_t ga = (size_t)(bm + (u >> 3)) * K2 + kt * 64 + (u & 7) * 8;
                    cpa(s0 + soA[i], A2 + ga);
                }
#pragma unroll
                for (int i = 0; i < 4; i++) {
                    int u = tid + i * 512;
                    size_t gb = (size_t)(bn + (u >> 3)) * K2 + kt * 64 + (u & 7) * 8;
                    cpa(s0 + 16384 + soB[i], B + gb);
                }
            }
            CP_COMMIT();
        };

        load_stage(0, 0);
        load_stage(1, 1);

        for (int kt = 0; kt < KT; kt++) {
            CP_WAIT1();
            __syncthreads();
            load_stage(kt + 2, (kt + 2) % 3);

            uint32_t s0 = sb + (kt % 3) * 49152;
#pragma unroll
            for (int ks = 0; ks < 4; ks++) {
                uint32_t ah[4][4], bh[4][2];
#pragma unroll
                for (int mt = 0; mt < 4; mt++) {
                    uint32_t off = SW128((uint32_t)((arow + mt * 16) * 128 + ks * 32 + acolb));
                    ldsm4(ah[mt], s0 + off);
                }
#pragma unroll
                for (int nt = 0; nt < 4; nt++) {
                    uint32_t off = SW128((uint32_t)((brow + nt * 8) * 128 + ks * 32 + bcolb));
                    ldsm2(bh[nt], s0 + 16384 + off);
                }
#pragma unroll
                for (int mt = 0; mt < 4; mt++)
#pragma unroll
                    for (int nt = 0; nt < 4; nt++)
                        mma16816(acc[mt][nt], ah[mt], bh[nt]);
            }
            __syncthreads();
        }

#pragma unroll
        for (int mt = 0; mt < 4; mt++) {
            int row0 = bm + wm + mt * 16 + q;
#pragma unroll
            for (int nt = 0; nt < 4; nt++) {
                int col = bn + wn + nt * 8 + i2;
                *(__half2*)(hw + (size_t)row0 * G4 + col) =
                    __floats2half2_rn(acc[mt][nt][0], acc[mt][nt][1]);
                *(__half2*)(hw + (size_t)(row0 + 8) * G4 + col) =
                    __floats2half2_rn(acc[mt][nt][2], acc[mt][nt][3]);
            }
        }
        __threadfence();
        __syncthreads();
        if (tid == 0) atomicAdd(&g_cntA[bid & 7], 1u);

        // ---- wait: hw for my 8 rows ------------------------------------------
        if (tid == 0) spin_ge(g_cntA + nb, 16u * (unsigned)(t + 1));
        __syncthreads();

        // ---------------- LSTM + attention: 8 rows, 64 thr/row ----------------
        if (tid < 128) red[tid] = 0.f;
        __syncthreads();

        const __half* xwr = XW + ((size_t)n * T_STEPS + t) * G4;
        float part[16];
#pragma unroll
        for (int l = 0; l < 16; l++) part[l] = 0.f;

#pragma unroll
        for (int k = 0; k < 16; k++) {
            int j = l64 + 64 * k;
            float ai = __half2float(hwr[j])        + __half2float(xwr[j]);
            float af = __half2float(hwr[1024 + j]) + __half2float(xwr[1024 + j]);
            float ao = __half2float(hwr[2048 + j]) + __half2float(xwr[2048 + j]);
            float ag = __half2float(hwr[3072 + j]) + __half2float(xwr[3072 + j]);
            float i_ = sigf(ai), f_ = sigf(af), o_ = sigf(ao), g_ = tanhf(ag);
            size_t cx = (size_t)n * H_DIM + j;
            float cn = f_ * c[cx] + i_ * g_;
            float hn = o_ * tanhf(cn);
            c[cx] = cn;
            out[((size_t)n * T_STEPS + t) * H_DIM + j] = hn;
            A2[(size_t)n * K2 + j] = __float2half_rn(hn);
            const __half2* rp = (const __half2*)(Afr + (size_t)j * 16);
#pragma unroll
            for (int qd = 0; qd < 8; qd++) {
                float2 f2 = __half22float2(rp[qd]);
                part[2 * qd]     += hn * f2.x;
                part[2 * qd + 1] += hn * f2.y;
            }
        }
#pragma unroll
        for (int l = 0; l < 16; l++) {
            float v = part[l];
            v += __shfl_down_sync(~0u, v, 16);
            v += __shfl_down_sync(~0u, v, 8);
            v += __shfl_down_sync(~0u, v, 4);
            v += __shfl_down_sync(~0u, v, 2);
            v += __shfl_down_sync(~0u, v, 1);
            if (lane == 0) atomicAdd(&red[row * 16 + l], v);
        }
        __syncthreads();
        if (l64 == 0) {
            float s[16], mx = -1e30f, sum = 0.f;
#pragma unroll
            for (int l = 0; l < 16; l++) { s[l] = red[row * 16 + l] * 0.03125f; mx = fmaxf(mx, s[l]); }
#pragma unroll
            for (int l = 0; l < 16; l++) { s[l] = __expf(s[l] - mx); sum += s[l]; }
            float inv = 1.f / sum;
#pragma unroll
            for (int l = 0; l < 16; l++) wsh[row * 16 + l] = s[l] * inv;
        }
        __syncthreads();
        float w[16];
#pragma unroll
        for (int l = 0; l < 16; l++) w[l] = wsh[row * 16 + l];
#pragma unroll
        for (int k = 0; k < 16; k++) {
            int j = l64 + 64 * k;
            const __half2* rp = (const __half2*)(Afr + (size_t)j * 16);
            float acc2 = 0.f;
#pragma unroll
            for (int qd = 0; qd < 8; qd++) {
                float2 f2 = __half22float2(rp[qd]);
                acc2 += w[2 * qd] * f2.x + w[2 * qd + 1] * f2.y;
            }
            A2[(size_t)n * K2 + H_DIM + j] = __float2half_rn(acc2);
        }
        __threadfence();
        __syncthreads();
        if (tid == 0) atomicAdd(&g_cntB[nb], 1u);
    }
}

// ---- prep: Af->fp16, h0=c0=mean, fill A2, zero counters ----------------------
__global__ void prep_kernel(const float* __restrict__ Af, __half* Af16,
                            float* c0, __half* A2) {
    __shared__ float h_sh[H_DIM];
    __shared__ float red[16];
    __shared__ float w_sh[16];
    const int n = blockIdx.x, tid = threadIdx.x;
    if (n == 0 && tid < 8) { g_cntA[tid] = 0u; g_cntB[tid] = 0u; }
    if (tid < 16) red[tid] = 0.f;
    const float* Ab = Af + (size_t)n * (H_DIM * 16);
    __half* A16b = Af16 + (size_t)n * (H_DIM * 16);
    for (int idx = tid; idx < H_DIM * 16 / 4; idx += 256) {
        float4 v = ((const float4*)Ab)[idx];
        ((__half2*)A16b)[2 * idx]     = __floats2half2_rn(v.x, v.y);
        ((__half2*)A16b)[2 * idx + 1] = __floats2half2_rn(v.z, v.w);
    }
#pragma unroll
    for (int k = 0; k < 4; k++) {
        int hh = tid + k * 256;
        const float4* src = (const float4*)(Ab + (size_t)hh * 16);
        float s = 0.f;
#pragma unroll
        for (int qd = 0; qd < 4; qd++) { float4 r = src[qd]; s += r.x + r.y + r.z + r.w; }
        float m = s * 0.0625f;
        c0[(size_t)n * H_DIM + hh] = m;
        h_sh[hh] = m;
        A2[(size_t)n * K2 + hh] = __float2half_rn(m);
    }
    __syncthreads();

    float part[16];
#pragma unroll
    for (int l = 0; l < 16; l++) part[l] = 0.f;
    float4 rows[4][4];
#pragma unroll
    for (int k = 0; k < 4; k++) {
        int hh = tid + k * 256;
        float hv = h_sh[hh];
        const float4* row = (const float4*)(Ab + (size_t)hh * 16);
#pragma unroll
        for (int qd = 0; qd < 4; qd++) rows[k][qd] = row[qd];
#pragma unroll
        for (int qd = 0; qd < 4; qd++) {
            part[4 * qd + 0] += hv * rows[k][qd].x;
            part[4 * qd + 1] += hv * rows[k][qd].y;
            part[4 * qd + 2] += hv * rows[k][qd].z;
            part[4 * qd + 3] += hv * rows[k][qd].w;
        }
    }
#pragma unroll
    for (int l = 0; l < 16; l++) {
        float v = part[l];
        v += __shfl_down_sync(~0u, v, 16);
        v += __shfl_down_sync(~0u, v, 8);
        v += __shfl_down_sync(~0u, v, 4);
        v += __shfl_down_sync(~0u, v, 2);
        v += __shfl_down_sync(~0u, v, 1);
        if ((tid & 31) == 0) atomicAdd(&red[l], v);
    }
    __syncthreads();
    if (tid == 0) {
        float s[16], mx = -1e30f, sum = 0.f;
#pragma unroll
        for (int l = 0; l < 16; l++) { s[l] = red[l] * 0.03125f; mx = fmaxf(mx, s[l]); }
#pragma unroll
        for (int l = 0; l < 16; l++) { s[l] = expf(s[l] - mx); sum += s[l]; }
        float inv = 1.f / sum;
#pragma unroll
        for (int l = 0; l < 16; l++) w_sh[l] = s[l] * inv;
    }
    __syncthreads();
    float w[16];
#pragma unroll
    for (int l = 0; l < 16; l++) w[l] = w_sh[l];
#pragma unroll
    for (int k = 0; k < 4; k++) {
        int hh = tid + k * 256;
        float acc = 0.f;
#pragma unroll
        for (int qd = 0; qd < 4; qd++) {
            acc += w[4 * qd + 0] * rows[k][qd].x + w[4 * qd + 1] * rows[k][qd].y
                 + w[4 * qd + 2] * rows[k][qd].z + w[4 * qd + 3] * rows[k][qd].w;
        }
        A2[(size_t)n * K2 + H_DIM + hh] = __float2half_rn(acc);
    }
}

__global__ void splitx_kernel(const float* __restrict__ x, __half* xo) {
    int i = blockIdx.x * blockDim.x + threadIdx.x;
    xo[i] = __float2half_rn(x[i]);
}
__global__ void twx_kernel(const float* __restrict__ Wx, __half* th) {
    int i = blockIdx.x * blockDim.x + threadIdx.x;
    int n = i >> 9, k = i & 511;
    th[i] = __float2half_rn(Wx[(size_t)k * G4 + n]);
}
__global__ void twc_kernel(const float* __restrict__ Wh, const float* __restrict__ Wa,
                           __half* th) {
    int i = blockIdx.x * blockDim.x + threadIdx.x;
    int n = i >> 11, k = i & 2047;
    float v = (k < H_DIM) ? Wh[(size_t)k * G4 + n] : Wa[(size_t)(k - H_DIM) * G4 + n];
    th[i] = __float2half_rn(v);
}

extern "C" void kernel_launch(void* const* d_in, const int* in_sizes, int n_in,
                              void* d_out, int out_size) {
    const float* x     = (const float*)d_in[0];
    const float* Af    = (const float*)d_in[1];
    const float* Wx    = (const float*)d_in[2];
    const float* Wh    = (const float*)d_in[3];
    const float* Wattn = (const float*)d_in[4];
    const float* b     = (const float*)d_in[5];
    float* out = (float*)d_out;

    float *c;
    __half *XW, *xv, *Wxp, *Wcp, *A2, *Af16, *hw;
    cudaGetSymbolAddress((void**)&XW, g_XW);
    cudaGetSymbolAddress((void**)&xv, g_x);
    cudaGetSymbolAddress((void**)&Wxp, g_Wxp);
    cudaGetSymbolAddress((void**)&Wcp, g_Wcp);
    cudaGetSymbolAddress((void**)&A2, g_A2);
    cudaGetSymbolAddress((void**)&Af16, g_Af16);
    cudaGetSymbolAddress((void**)&c, g_c);
    cudaGetSymbolAddress((void**)&hw, g_hw);

    cudaFuncSetAttribute(gemm_xw_kernel, cudaFuncAttributeMaxDynamicSharedMemorySize, GSMEM);
    cudaFuncSetAttribute(persist_kernel, cudaFuncAttributeMaxDynamicSharedMemorySize, GSMEM2);

    prep_kernel<<<N_BATCH, 256>>>(Af, Af16, c, A2);
    splitx_kernel<<<(N_BATCH * T_STEPS * D_IN) / 256, 256>>>(x, xv);
    twx_kernel<<<(G4 * D_IN) / 256, 256>>>(Wx, Wxp);
    twc_kernel<<<(G4 * K2) / 256, 256>>>(Wh, Wattn, Wcp);

    // XW = x @ Wx + b for all t  (M = 65536, 1 MMA, fp16 out)
    {
        dim3 grid(G4 / 128, (N_BATCH * T_STEPS) / 128);
        gemm_xw_kernel<<<grid, 256, GSMEM>>>(xv, D_IN, Wxp, D_IN, b, XW, D_IN, G4);
    }

    // single persistent kernel: per-block producer/consumer pipelining
    persist_kernel<<<128, 512, GSMEM2>>>(A2, Wcp, hw, XW, Af16, c, out);
}

// round 17
// speedup vs baseline: 1.0179x; 1.0179x over previous
#include <cuda_runtime.h>
#include <cuda_fp16.h>
#include <cstdint>

#define N_BATCH 1024
#define T_STEPS 64
#define D_IN    512
#define H_DIM   1024
#define G4      4096
#define K2      2048

__device__ __half g_XW [(size_t)N_BATCH * T_STEPS * G4];
__device__ __half g_x  [(size_t)N_BATCH * T_STEPS * D_IN];
__device__ __half g_Wxp[(size_t)G4 * D_IN];
__device__ __half g_Wcp[(size_t)G4 * K2];
__device__ __half g_A2 [(size_t)N_BATCH * K2];
__device__ __half g_Af16[(size_t)N_BATCH * H_DIM * 16];
__device__ float  g_c  [(size_t)N_BATCH * H_DIM];
__device__ __half g_hw [(size_t)N_BATCH * G4];
__device__ unsigned int g_cnt[8];    // A2-ready per bm block (monotonic)

// ---- helpers ----
__device__ __forceinline__ uint32_t s2u(const void* p) {
    uint32_t a;
    asm("{.reg .u64 t; cvta.to.shared.u64 t, %1; cvt.u32.u64 %0, t;}" : "=r"(a) : "l"(p));
    return a;
}
#define SW128(o) ((o) ^ (((o) >> 3) & 0x70))
__device__ __forceinline__ void cpa(uint32_t s, const void* g) {
    asm volatile("cp.async.cg.shared.global [%0], [%1], 16;" :: "r"(s), "l"(g));
}
#define CP_COMMIT() asm volatile("cp.async.commit_group;" ::: "memory")
#define CP_WAIT1()  asm volatile("cp.async.wait_group 1;" ::: "memory")

__device__ __forceinline__ void mma16816(float* c, const uint32_t* a, const uint32_t* b) {
    asm volatile("mma.sync.aligned.m16n8k16.row.col.f32.f16.f16.f32 "
        "{%0,%1,%2,%3}, {%4,%5,%6,%7}, {%8,%9}, {%0,%1,%2,%3};"
        : "+f"(c[0]), "+f"(c[1]), "+f"(c[2]), "+f"(c[3])
        : "r"(a[0]), "r"(a[1]), "r"(a[2]), "r"(a[3]), "r"(b[0]), "r"(b[1]));
}
__device__ __forceinline__ void ldsm4(uint32_t* r, uint32_t a) {
    asm volatile("ldmatrix.sync.aligned.m8n8.x4.shared.b16 {%0,%1,%2,%3}, [%4];"
        : "=r"(r[0]), "=r"(r[1]), "=r"(r[2]), "=r"(r[3]) : "r"(a));
}
__device__ __forceinline__ void ldsm2(uint32_t* r, uint32_t a) {
    asm volatile("ldmatrix.sync.aligned.m8n8.x2.shared.b16 {%0,%1}, [%2];"
        : "=r"(r[0]), "=r"(r[1]) : "r"(a));
}
__device__ __forceinline__ float sigf(float x) { return 1.f / (1.f + __expf(-x)); }

// ===== XW GEMM: 128x128, BK=64, 3-stage, 1 MMA, fp16 output =================
#define GSMEM (3 * 32768)
__global__ void __launch_bounds__(256, 1)
gemm_xw_kernel(const __half* __restrict__ A, int lda,
               const __half* __restrict__ B, int ldb,
               const float* __restrict__ bias, __half* __restrict__ C, int K, int Nc) {
    extern __shared__ char smx[];
    const uint32_t sb = s2u(smx);
    const int tid = threadIdx.x, wid = tid >> 5, lane = tid & 31;
    const int bm = blockIdx.y * 128, bn = blockIdx.x * 128;
    const int wm = (wid >> 2) * 64, wn = (wid & 3) * 32;

    uint32_t so[4];
#pragma unroll
    for (int i = 0; i < 4; i++)
        so[i] = SW128((uint32_t)(((tid >> 3) + i * 32) * 128 + (tid & 7) * 16));

    const int KT = K / 64;
    float acc[4][4][4];
#pragma unroll
    for (int mt = 0; mt < 4; mt++)
#pragma unroll
        for (int nt = 0; nt < 4; nt++)
#pragma unroll
            for (int v = 0; v < 4; v++) acc[mt][nt][v] = 0.f;

    auto load_stage = [&](int kt, int st) {
        if (kt < KT) {
            uint32_t s0 = sb + st * 32768;
#pragma unroll
            for (int i = 0; i < 4; i++) {
                int r = (tid >> 3) + i * 32;
                size_t ga = (size_t)(bm + r) * lda + kt * 64 + (tid & 7) * 8;
                size_t gb = (size_t)(bn + r) * ldb + kt * 64 + (tid & 7) * 8;
                cpa(s0 + so[i],         A + ga);
                cpa(s0 + 16384 + so[i], B + gb);
            }
        }
        CP_COMMIT();
    };

    load_stage(0, 0);
    load_stage(1, 1);

    const int arow  = wm + (lane & 7) + ((lane >> 3) & 1) * 8;
    const int acolb = ((lane >> 4) & 1) * 16;
    const int brow  = wn + (lane & 7);
    const int bcolb = ((lane >> 3) & 1) * 16;

    for (int kt = 0; kt < KT; kt++) {
        CP_WAIT1();
        __syncthreads();
        load_stage(kt + 2, (kt + 2) % 3);

        uint32_t s0 = sb + (kt % 3) * 32768;
#pragma unroll
        for (int ks = 0; ks < 4; ks++) {
            uint32_t ah[4][4], bh[4][2];
#pragma unroll
            for (int mt = 0; mt < 4; mt++) {
                uint32_t off = SW128((uint32_t)((arow + mt * 16) * 128 + ks * 32 + acolb));
                ldsm4(ah[mt], s0 + off);
            }
#pragma unroll
            for (int nt = 0; nt < 4; nt++) {
                uint32_t off = SW128((uint32_t)((brow + nt * 8) * 128 + ks * 32 + bcolb));
                ldsm2(bh[nt], s0 + 16384 + off);
            }
#pragma unroll
            for (int mt = 0; mt < 4; mt++)
#pragma unroll
                for (int nt = 0; nt < 4; nt++)
                    mma16816(acc[mt][nt], ah[mt], bh[nt]);
        }
        __syncthreads();
    }

    const int q = lane >> 2, i2 = (lane & 3) * 2;
#pragma unroll
    for (int mt = 0; mt < 4; mt++) {
        int row0 = bm + wm + mt * 16 + q;
#pragma unroll
        for (int nt = 0; nt < 4; nt++) {
            int col = bn + wn + nt * 8 + i2;
            float2 bb = *(const float2*)(bias + col);
            *(__half2*)(C + (size_t)row0 * Nc + col) =
                __floats2half2_rn(acc[mt][nt][0] + bb.x, acc[mt][nt][1] + bb.y);
            *(__half2*)(C + (size_t)(row0 + 8) * Nc + col) =
                __floats2half2_rn(acc[mt][nt][2] + bb.x, acc[mt][nt][3] + bb.y);
        }
    }
}

// ===== STEP (lstm-first): launch t does LSTM(t-1) then GEMM(t) ===============
// t in [0,64]; t=0: GEMM only. t=64: LSTM only.
#define GSMEM2 (3 * 49152)
__global__ void __launch_bounds__(512, 1)
step_kernel(__half* __restrict__ A2, const __half* __restrict__ B,
            __half* __restrict__ hw,
            const __half* __restrict__ XW,
            const __half* __restrict__ Af16,
            float* __restrict__ c,
            float* __restrict__ out, int t) {
    extern __shared__ char smx[];
    const uint32_t sb = s2u(smx);
    const int tid = threadIdx.x, wid = tid >> 5, lane = tid & 31;
    const int bid = (int)blockIdx.x;
    const int bm = (bid & 7) * 128, bn = (bid >> 3) * 256;
    const int wm = (wid >> 3) * 64, wn = (wid & 7) * 32;
    const int KT = K2 / 64;

    // ============ LSTM + attention for step t-1 (8 rows, 64 thr/row) ========
    if (t > 0) {
        const int ts = t - 1;
        const int n0 = bid * 8;
        const int row = tid >> 6, l64 = tid & 63;
        const int n = n0 + row;
        const __half* hwr = hw + (size_t)n * G4;
        const __half* xwr = XW + ((size_t)n * T_STEPS + ts) * G4;
        const __half* Afr = Af16 + (size_t)n * (H_DIM * 16);

        float* red = (float*)smx;       // 8 x 16
        float* wsh = red + 128;
        if (tid < 128) red[tid] = 0.f;
        __syncthreads();

        float part[16];
#pragma unroll
        for (int l = 0; l < 16; l++) part[l] = 0.f;

#pragma unroll
        for (int k = 0; k < 16; k++) {
            int j = l64 + 64 * k;
            float ai = __half2float(hwr[j])        + __half2float(xwr[j]);
            float af = __half2float(hwr[1024 + j]) + __half2float(xwr[1024 + j]);
            float ao = __half2float(hwr[2048 + j]) + __half2float(xwr[2048 + j]);
            float ag = __half2float(hwr[3072 + j]) + __half2float(xwr[3072 + j]);
            float i_ = sigf(ai), f_ = sigf(af), o_ = sigf(ao), g_ = tanhf(ag);
            size_t cx = (size_t)n * H_DIM + j;
            float cn = f_ * c[cx] + i_ * g_;
            float hn = o_ * tanhf(cn);
            c[cx] = cn;
            out[((size_t)n * T_STEPS + ts) * H_DIM + j] = hn;
            A2[(size_t)n * K2 + j] = __float2half_rn(hn);
            const __half2* rp = (const __half2*)(Afr + (size_t)j * 16);
#pragma unroll
            for (int qd = 0; qd < 8; qd++) {
                float2 f2 = __half22float2(rp[qd]);
                part[2 * qd]     += hn * f2.x;
                part[2 * qd + 1] += hn * f2.y;
            }
        }
#pragma unroll
        for (int l = 0; l < 16; l++) {
            float v = part[l];
            v += __shfl_down_sync(~0u, v, 16);
            v += __shfl_down_sync(~0u, v, 8);
            v += __shfl_down_sync(~0u, v, 4);
            v += __shfl_down_sync(~0u, v, 2);
            v += __shfl_down_sync(~0u, v, 1);
            if (lane == 0) atomicAdd(&red[row * 16 + l], v);
        }
        __syncthreads();
        if (l64 == 0) {
            float s[16], mx = -1e30f, sum = 0.f;
#pragma unroll
            for (int l = 0; l < 16; l++) { s[l] = red[row * 16 + l] * 0.03125f; mx = fmaxf(mx, s[l]); }
#pragma unroll
            for (int l = 0; l < 16; l++) { s[l] = __expf(s[l] - mx); sum += s[l]; }
            float inv = 1.f / sum;
#pragma unroll
            for (int l = 0; l < 16; l++) wsh[row * 16 + l] = s[l] * inv;
        }
        __syncthreads();
        float w[16];
#pragma unroll
        for (int l = 0; l < 16; l++) w[l] = wsh[row * 16 + l];
#pragma unroll
        for (int k = 0; k < 16; k++) {
            int j = l64 + 64 * k;
            const __half2* rp = (const __half2*)(Afr + (size_t)j * 16);
            float acc2 = 0.f;
#pragma unroll
            for (int qd = 0; qd < 8; qd++) {
                float2 f2 = __half22float2(rp[qd]);
                acc2 += w[2 * qd] * f2.x + w[2 * qd + 1] * f2.y;
            }
            A2[(size_t)n * K2 + H_DIM + j] = __float2half_rn(acc2);
        }
        __threadfence();
        __syncthreads();
        if (tid == 0) atomicAdd(&g_cnt[bid >> 4], 1u);   // my rows' bm block
    }

    if (t >= T_STEPS) return;                            // final launch: lstm only

    // ============ spin: A2 for my bm block complete (16 lstm posts) ==========
    if (t > 0) {
        if (tid == 0) {
            unsigned v;
            const unsigned target = 16u * (unsigned)t;
            do {
                asm volatile("ld.acquire.gpu.u32 %0, [%1];"
                             : "=r"(v) : "l"(g_cnt + (bid & 7)) : "memory");
                if (v < target) __nanosleep(64);
            } while (v < target);
        }
        __syncthreads();
    }

    // ============ GEMM(t): 128x256 tile, BK=64, 3-stage ======================
    uint32_t soA[2], soB[4];
#pragma unroll
    for (int i = 0; i < 2; i++) {
        int u = tid + i * 512;
        soA[i] = SW128((uint32_t)((u >> 3) * 128 + (u & 7) * 16));
    }
#pragma unroll
    for (int i = 0; i < 4; i++) {
        int u = tid + i * 512;
        soB[i] = SW128((uint32_t)((u >> 3) * 128 + (u & 7) * 16));
    }

    float acc[4][4][4];
#pragma unroll
    for (int mt = 0; mt < 4; mt++)
#pragma unroll
        for (int nt = 0; nt < 4; nt++)
#pragma unroll
            for (int v = 0; v < 4; v++) acc[mt][nt][v] = 0.f;

    auto load_stage = [&](int kt, int st) {
        if (kt < KT) {
            uint32_t s0 = sb + st * 49152;
#pragma unroll
            for (int i = 0; i < 2; i++) {
                int u = tid + i * 512;
                size_t ga = (size_t)(bm + (u >> 3)) * K2 + kt * 64 + (u & 7) * 8;
                cpa(s0 + soA[i], A2 + ga);
            }
#pragma unroll
            for (int i = 0; i < 4; i++) {
                int u = tid + i * 512;
                size_t gb = (size_t)(bn + (u >> 3)) * K2 + kt * 64 + (u & 7) * 8;
                cpa(s0 + 16384 + soB[i], B + gb);
            }
        }
        CP_COMMIT();
    };

    load_stage(0, 0);
    load_stage(1, 1);

    const int arow  = wm + (lane & 7) + ((lane >> 3) & 1) * 8;
    const int acolb = ((lane >> 4) & 1) * 16;
    const int brow  = wn + (lane & 7);
    const int bcolb = ((lane >> 3) & 1) * 16;

    for (int kt = 0; kt < KT; kt++) {
        CP_WAIT1();
        __syncthreads();
        load_stage(kt + 2, (kt + 2) % 3);

        uint32_t s0 = sb + (kt % 3) * 49152;
#pragma unroll
        for (int ks = 0; ks < 4; ks++) {
            uint32_t ah[4][4], bh[4][2];
#pragma unroll
            for (int mt = 0; mt < 4; mt++) {
                uint32_t off = SW128((uint32_t)((arow + mt * 16) * 128 + ks * 32 + acolb));
                ldsm4(ah[mt], s0 + off);
            }
#pragma unroll
            for (int nt = 0; nt < 4; nt++) {
                uint32_t off = SW128((uint32_t)((brow + nt * 8) * 128 + ks * 32 + bcolb));
                ldsm2(bh[nt], s0 + 16384 + off);
            }
#pragma unroll
            for (int mt = 0; mt < 4; mt++)
#pragma unroll
                for (int nt = 0; nt < 4; nt++)
                    mma16816(acc[mt][nt], ah[mt], bh[nt]);
        }
        __syncthreads();
    }

    const int q = lane >> 2, i2 = (lane & 3) * 2;
#pragma unroll
    for (int mt = 0; mt < 4; mt++) {
        int row0 = bm + wm + mt * 16 + q;
#pragma unroll
        for (int nt = 0; nt < 4; nt++) {
            int col = bn + wn + nt * 8 + i2;
            *(__half2*)(hw + (size_t)row0 * G4 + col) =
                __floats2half2_rn(acc[mt][nt][0], acc[mt][nt][1]);
            *(__half2*)(hw + (size_t)(row0 + 8) * G4 + col) =
                __floats2half2_rn(acc[mt][nt][2], acc[mt][nt][3]);
        }
    }
}

// ---- prep: Af->fp16, h0=c0=mean, fill A2, zero counters ----------------------
__global__ void prep_kernel(const float* __restrict__ Af, __half* Af16,
                            float* c0, __half* A2) {
    __shared__ float h_sh[H_DIM];
    __shared__ float red[16];
    __shared__ float w_sh[16];
    const int n = blockIdx.x, tid = threadIdx.x;
    if (n == 0 && tid < 8) g_cnt[tid] = 0u;
    if (tid < 16) red[tid] = 0.f;
    const float* Ab = Af + (size_t)n * (H_DIM * 16);
    __half* A16b = Af16 + (size_t)n * (H_DIM * 16);
    for (int idx = tid; idx < H_DIM * 16 / 4; idx += 256) {
        float4 v = ((const float4*)Ab)[idx];
        ((__half2*)A16b)[2 * idx]     = __floats2half2_rn(v.x, v.y);
        ((__half2*)A16b)[2 * idx + 1] = __floats2half2_rn(v.z, v.w);
    }
#pragma unroll
    for (int k = 0; k < 4; k++) {
        int hh = tid + k * 256;
        const float4* src = (const float4*)(Ab + (size_t)hh * 16);
        float s = 0.f;
#pragma unroll
        for (int qd = 0; qd < 4; qd++) { float4 r = src[qd]; s += r.x + r.y + r.z + r.w; }
        float m = s * 0.0625f;
        c0[(size_t)n * H_DIM + hh] = m;
        h_sh[hh] = m;
        A2[(size_t)n * K2 + hh] = __float2half_rn(m);
    }
    __syncthreads();

    float part[16];
#pragma unroll
    for (int l = 0; l < 16; l++) part[l] = 0.f;
    float4 rows[4][4];
#pragma unroll
    for (int k = 0; k < 4; k++) {
        int hh = tid + k * 256;
        float hv = h_sh[hh];
        const float4* row = (const float4*)(Ab + (size_t)hh * 16);
#pragma unroll
        for (int qd = 0; qd < 4; qd++) rows[k][qd] = row[qd];
#pragma unroll
        for (int qd = 0; qd < 4; qd++) {
            part[4 * qd + 0] += hv * rows[k][qd].x;
            part[4 * qd + 1] += hv * rows[k][qd].y;
            part[4 * qd + 2] += hv * rows[k][qd].z;
            part[4 * qd + 3] += hv * rows[k][qd].w;
        }
    }
#pragma unroll
    for (int l = 0; l < 16; l++) {
        float v = part[l];
        v += __shfl_down_sync(~0u, v, 16);
        v += __shfl_down_sync(~0u, v, 8);
        v += __shfl_down_sync(~0u, v, 4);
        v += __shfl_down_sync(~0u, v, 2);
        v += __shfl_down_sync(~0u, v, 1);
        if ((tid & 31) == 0) atomicAdd(&red[l], v);
    }
    __syncthreads();
    if (tid == 0) {
        float s[16], mx = -1e30f, sum = 0.f;
#pragma unroll
        for (int l = 0; l < 16; l++) { s[l] = red[l] * 0.03125f; mx = fmaxf(mx, s[l]); }
#pragma unroll
        for (int l = 0; l < 16; l++) { s[l] = expf(s[l] - mx); sum += s[l]; }
        float inv = 1.f / sum;
#pragma unroll
        for (int l = 0; l < 16; l++) w_sh[l] = s[l] * inv;
    }
    __syncthreads();
    float w[16];
#pragma unroll
    for (int l = 0; l < 16; l++) w[l] = w_sh[l];
#pragma unroll
    for (int k = 0; k < 4; k++) {
        int hh = tid + k * 256;
        float acc = 0.f;
#pragma unroll
        for (int qd = 0; qd < 4; qd++) {
            acc += w[4 * qd + 0] * rows[k][qd].x + w[4 * qd + 1] * rows[k][qd].y
                 + w[4 * qd + 2] * rows[k][qd].z + w[4 * qd + 3] * rows[k][qd].w;
        }
        A2[(size_t)n * K2 + H_DIM + hh] = __float2half_rn(acc);
    }
}

__global__ void splitx_kernel(const float* __restrict__ x, __half* xo) {
    int i = blockIdx.x * blockDim.x + threadIdx.x;
    xo[i] = __float2half_rn(x[i]);
}
__global__ void twx_kernel(const float* __restrict__ Wx, __half* th) {
    int i = blockIdx.x * blockDim.x + threadIdx.x;
    int n = i >> 9, k = i & 511;
    th[i] = __float2half_rn(Wx[(size_t)k * G4 + n]);
}
__global__ void twc_kernel(const float* __restrict__ Wh, const float* __restrict__ Wa,
                           __half* th) {
    int i = blockIdx.x * blockDim.x + threadIdx.x;
    int n = i >> 11, k = i & 2047;
    float v = (k < H_DIM) ? Wh[(size_t)k * G4 + n] : Wa[(size_t)(k - H_DIM) * G4 + n];
    th[i] = __float2half_rn(v);
}

extern "C" void kernel_launch(void* const* d_in, const int* in_sizes, int n_in,
                              void* d_out, int out_size) {
    const float* x     = (const float*)d_in[0];
    const float* Af    = (const float*)d_in[1];
    const float* Wx    = (const float*)d_in[2];
    const float* Wh    = (const float*)d_in[3];
    const float* Wattn = (const float*)d_in[4];
    const float* b     = (const float*)d_in[5];
    float* out = (float*)d_out;

    float *c;
    __half *XW, *xv, *Wxp, *Wcp, *A2, *Af16, *hw;
    cudaGetSymbolAddress((void**)&XW, g_XW);
    cudaGetSymbolAddress((void**)&xv, g_x);
    cudaGetSymbolAddress((void**)&Wxp, g_Wxp);
    cudaGetSymbolAddress((void**)&Wcp, g_Wcp);
    cudaGetSymbolAddress((void**)&A2, g_A2);
    cudaGetSymbolAddress((void**)&Af16, g_Af16);
    cudaGetSymbolAddress((void**)&c, g_c);
    cudaGetSymbolAddress((void**)&hw, g_hw);

    cudaFuncSetAttribute(gemm_xw_kernel, cudaFuncAttributeMaxDynamicSharedMemorySize, GSMEM);
    cudaFuncSetAttribute(step_kernel, cudaFuncAttributeMaxDynamicSharedMemorySize, GSMEM2);

    prep_kernel<<<N_BATCH, 256>>>(Af, Af16, c, A2);
    splitx_kernel<<<(N_BATCH * T_STEPS * D_IN) / 256, 256>>>(x, xv);
    twx_kernel<<<(G4 * D_IN) / 256, 256>>>(Wx, Wxp);
    twc_kernel<<<(G4 * K2) / 256, 256>>>(Wh, Wattn, Wcp);

    // XW = x @ Wx + b for all t  (M = 65536, 1 MMA, fp16 out)
    {
        dim3 grid(G4 / 128, (N_BATCH * T_STEPS) / 128);
        gemm_xw_kernel<<<grid, 256, GSMEM>>>(xv, D_IN, Wxp, D_IN, b, XW, D_IN, G4);
    }

    // lstm-first pipeline: launch t does LSTM(t-1) then GEMM(t); t=64 lstm only
    for (int t = 0; t <= T_STEPS; t++) {
        step_kernel<<<128, 512, GSMEM2>>>(A2, Wcp, hw, XW, Af16, c, out, t);
    }
}